// round 12
// baseline (speedup 1.0000x reference)
#include <cuda_runtime.h>
#include <cuda_fp16.h>
#include <math.h>
#include <stdint.h>

#define MTOK  16384
#define CDIM  768
#define TSEQ  1024
#define BATCH 16
#define NHEAD 8
#define HDIM  96

// ================= scratch (no allocation allowed) =================
__device__ __half g_h  [(size_t)MTOK * CDIM];
__device__ __half g_qkv[(size_t)MTOK * 3 * CDIM];
__device__ __half g_y  [(size_t)MTOK * CDIM];
__device__ float  g_x1 [(size_t)MTOK * CDIM];
__device__ __half g_h2 [(size_t)MTOK * 4 * CDIM];
__device__ __half g_wqkv[(size_t)CDIM * 3 * CDIM];
__device__ __half g_wproj[(size_t)CDIM * CDIM];
__device__ __half g_wfc [(size_t)CDIM * 4 * CDIM];
__device__ __half g_wfc2[(size_t)4 * CDIM * CDIM];

__device__ __forceinline__ float gelu_f(float x) {
    const float x3 = x * x * x;
    return 0.5f * x * (1.0f + tanhf(0.7978845608028654f * (x + 0.044715f * x3)));
}
__device__ __forceinline__ uint32_t smem_u32(const void* p) {
    return (uint32_t)__cvta_generic_to_shared(p);
}
__device__ __forceinline__ void cp16(uint32_t dst, const void* src) {
    asm volatile("cp.async.cg.shared.global [%0], [%1], 16;\n" :: "r"(dst), "l"(src));
}
#define CP_COMMIT() asm volatile("cp.async.commit_group;\n" ::: "memory")
#define CP_WAIT1()  asm volatile("cp.async.wait_group 1;\n" ::: "memory")

__device__ __forceinline__ void ldsm_x4(
    uint32_t& r0, uint32_t& r1, uint32_t& r2, uint32_t& r3, uint32_t addr)
{
    asm volatile("ldmatrix.sync.aligned.m8n8.x4.shared.b16 {%0,%1,%2,%3}, [%4];"
        : "=r"(r0), "=r"(r1), "=r"(r2), "=r"(r3) : "r"(addr));
}
__device__ __forceinline__ void ldsm_x4_t(
    uint32_t& r0, uint32_t& r1, uint32_t& r2, uint32_t& r3, uint32_t addr)
{
    asm volatile("ldmatrix.sync.aligned.m8n8.x4.trans.shared.b16 {%0,%1,%2,%3}, [%4];"
        : "=r"(r0), "=r"(r1), "=r"(r2), "=r"(r3) : "r"(addr));
}
__device__ __forceinline__ void mma16816(
    float* c, const uint32_t* a, uint32_t b0, uint32_t b1)
{
    asm volatile(
        "mma.sync.aligned.m16n8k16.row.col.f32.f16.f16.f32 "
        "{%0,%1,%2,%3},{%4,%5,%6,%7},{%8,%9},{%0,%1,%2,%3};"
        : "+f"(c[0]), "+f"(c[1]), "+f"(c[2]), "+f"(c[3])
        : "r"(a[0]), "r"(a[1]), "r"(a[2]), "r"(a[3]), "r"(b0), "r"(b1));
}
__device__ __forceinline__ uint32_t packh2(float a, float b) {
    __half2 h = __floats2half2_rn(a, b);
    return *(uint32_t*)&h;
}

// ================= fused weight f32 -> fp16 =================
__global__ __launch_bounds__(256) void wconv4_kernel(
    const float* __restrict__ s0, __half* __restrict__ d0, int n0,
    const float* __restrict__ s1, __half* __restrict__ d1, int n1,
    const float* __restrict__ s2, __half* __restrict__ d2, int n2,
    const float* __restrict__ s3, __half* __restrict__ d3, int n3)
{
    int i = blockIdx.x * 256 + threadIdx.x;
    const float* src; __half* dst;
    if (i < n0) { src = s0; dst = d0; }
    else if ((i -= n0) < n1) { src = s1; dst = d1; }
    else if ((i -= n1) < n2) { src = s2; dst = d2; }
    else if ((i -= n2) < n3) { src = s3; dst = d3; }
    else return;
    float4 v = ((const float4*)src)[i];
    __half2 a = __floats2half2_rn(v.x, v.y);
    __half2 b = __floats2half2_rn(v.z, v.w);
    *(uint2*)(dst + (size_t)i * 4) = make_uint2(*(uint32_t*)&a, *(uint32_t*)&b);
}

// ================= layernorm (f32 in -> fp16 out) =================
__global__ __launch_bounds__(256) void ln_kernel(
    const float* __restrict__ x, const float* __restrict__ g,
    const float* __restrict__ b, __half* __restrict__ out)
{
    const int row = blockIdx.x;
    const int tid = threadIdx.x;
    const float* xr = x + (size_t)row * CDIM;
    float vals[3];
    float s = 0.f, s2 = 0.f;
#pragma unroll
    for (int j = 0; j < 3; j++) {
        float t = xr[tid + 256 * j];
        vals[j] = t; s += t; s2 += t * t;
    }
#pragma unroll
    for (int o = 16; o > 0; o >>= 1) {
        s  += __shfl_xor_sync(0xffffffffu, s,  o);
        s2 += __shfl_xor_sync(0xffffffffu, s2, o);
    }
    __shared__ float rs[8], rs2[8];
    const int wid = tid >> 5, lane = tid & 31;
    if (lane == 0) { rs[wid] = s; rs2[wid] = s2; }
    __syncthreads();
    s = 0.f; s2 = 0.f;
#pragma unroll
    for (int w = 0; w < 8; w++) { s += rs[w]; s2 += rs2[w]; }
    const float mu  = s * (1.0f / CDIM);
    const float var = s2 * (1.0f / CDIM) - mu * mu;
    const float rstd = rsqrtf(var + 1e-5f);
#pragma unroll
    for (int j = 0; j < 3; j++) {
        const int c = tid + 256 * j;
        out[(size_t)row * CDIM + c] = __float2half_rn((vals[j] - mu) * rstd * g[c] + b[c]);
    }
}

// ================= raw-mma fp16 GEMM, BK=64, 3-stage, direct epilogue ======
// block 128x128, 128 threads (4 warps 2x2), warp tile 64x64 = 4 m16 x 8 n8.
#define AS_OFF 0
#define BS_OFF (3 * 128 * 72 * 2)
#define GEMM_SMEM (BS_OFF + 3 * 64 * 136 * 2)

// EPI: 0 = bias -> half ; 1 = bias+res(f32) -> f32 ; 2 = bias+gelu -> half
template <int EPI>
__global__ __launch_bounds__(128) void hgemm_kernel(
    const __half* __restrict__ A, const __half* __restrict__ B,
    const float* __restrict__ bias, const float* __restrict__ res,
    float* __restrict__ Cf, __half* __restrict__ Ch, int N, int K)
{
    extern __shared__ char dsm[];
    __half* Asb = (__half*)(dsm + AS_OFF);    // [3][128][72]
    __half* Bsb = (__half*)(dsm + BS_OFF);    // [3][64][136]

    const int tid  = threadIdx.x;
    const int wid  = tid >> 5, lane = tid & 31;
    const int wm   = wid >> 1;
    const int wn   = wid & 1;
    const int g    = lane >> 2, q4 = lane & 3;
    const int grp  = lane >> 3, lr = lane & 7;
    const int bx   = blockIdx.x, by = blockIdx.y;

    float c[4][8][4];
#pragma unroll
    for (int mi = 0; mi < 4; mi++)
#pragma unroll
        for (int j = 0; j < 8; j++)
#pragma unroll
            for (int e = 0; e < 4; e++) c[mi][j][e] = 0.f;

    const __half* Agm = A + (size_t)(by * 128) * K;
    const __half* Bgm = B + bx * 128;
    const int nk = K >> 6;

    const int arb = tid >> 3, ak = (tid & 7) * 8;
    const int bkb = tid >> 4, bc = (tid & 15) * 8;

    auto copy_tile = [&](int s, int kt) {
        const __half* An = Agm + kt * 64;
        const __half* Bn = Bgm + (size_t)(kt * 64) * N;
#pragma unroll
        for (int it = 0; it < 8; it++) {
            const int ar = arb + it * 16;
            const int bk = bkb + it * 8;
            cp16(smem_u32(&Asb[((s * 128) + ar) * 72 + ak]), An + (size_t)ar * K + ak);
            cp16(smem_u32(&Bsb[((s * 64) + bk) * 136 + bc]), Bn + (size_t)bk * N + bc);
        }
    };

    copy_tile(0, 0); CP_COMMIT();
    copy_tile(1, 1); CP_COMMIT();

    // ldsm base offsets (within a stage)
    const int a_row_off = wm * 64 + ((grp & 1) ? 8 : 0) + lr;  // + mi*16
    const int a_col_off = (grp & 2) ? 8 : 0;                   // + ks*16
    const int b_row_off = lr + ((grp & 1) ? 8 : 0);            // + ks*16
    const int b_col_off = wn * 64 + ((grp & 2) ? 8 : 0);       // + jn*16

    int buf = 0, cslot = 2;
    for (int kt = 0; kt < nk; ++kt) {
        CP_WAIT1();
        __syncthreads();
        if (kt + 2 < nk) copy_tile(cslot, kt + 2);
        CP_COMMIT();

#pragma unroll
        for (int ks = 0; ks < 4; ks++) {
            uint32_t a[4][4];
#pragma unroll
            for (int mi = 0; mi < 4; mi++)
                ldsm_x4(a[mi][0], a[mi][1], a[mi][2], a[mi][3],
                    smem_u32(&Asb[((buf * 128) + a_row_off + mi * 16) * 72
                                  + ks * 16 + a_col_off]));
#pragma unroll
            for (int jn = 0; jn < 4; jn++) {
                uint32_t b0, b1, b2, b3;
                ldsm_x4_t(b0, b1, b2, b3,
                    smem_u32(&Bsb[((buf * 64) + ks * 16 + b_row_off) * 136
                                  + jn * 16 + b_col_off]));
#pragma unroll
                for (int mi = 0; mi < 4; mi++) {
                    mma16816(c[mi][2 * jn],     a[mi], b0, b1);
                    mma16816(c[mi][2 * jn + 1], a[mi], b2, b3);
                }
            }
        }
        buf   = (buf   == 2) ? 0 : buf + 1;
        cslot = (cslot == 2) ? 0 : cslot + 1;
    }

    // ---- direct-register epilogue ----
    // c[mi][j]: rows rA = wm*64+mi*16+g, rB = rA+8 ; cols j*8 + q4*2 (+1)
#pragma unroll
    for (int mi = 0; mi < 4; mi++) {
        const int rA = by * 128 + wm * 64 + mi * 16 + g;
        const int rB = rA + 8;
#pragma unroll
        for (int j = 0; j < 8; j++) {
            const int col = bx * 128 + wn * 64 + j * 8 + q4 * 2;
            const float2 bb = *(const float2*)(bias + col);
            float v0 = c[mi][j][0] + bb.x;
            float v1 = c[mi][j][1] + bb.y;
            float v2 = c[mi][j][2] + bb.x;
            float v3 = c[mi][j][3] + bb.y;
            if (EPI == 1) {
                const size_t iA = (size_t)rA * N + col;
                const size_t iB = (size_t)rB * N + col;
                const float2 rAv = *(const float2*)(res + iA);
                const float2 rBv = *(const float2*)(res + iB);
                v0 += rAv.x; v1 += rAv.y; v2 += rBv.x; v3 += rBv.y;
                *(float2*)(Cf + iA) = make_float2(v0, v1);
                *(float2*)(Cf + iB) = make_float2(v2, v3);
            } else {
                if (EPI == 2) {
                    v0 = gelu_f(v0); v1 = gelu_f(v1);
                    v2 = gelu_f(v2); v3 = gelu_f(v3);
                }
                *(uint32_t*)(Ch + (size_t)rA * N + col) = packh2(v0, v1);
                *(uint32_t*)(Ch + (size_t)rB * N + col) = packh2(v2, v3);
            }
        }
    }
}

// ================= FA2 attention (unchanged from R11) =================
#define ATTN_SMEM ((128 + 64 + 64) * 104 * 2)

__global__ __launch_bounds__(128) void attn_kernel(
    const __half* __restrict__ qkv, __half* __restrict__ y)
{
    extern __shared__ __half asm_[];
    __half* Qs = asm_;
    __half* Ks = asm_ + 128 * 104;
    __half* Vs = asm_ + 192 * 104;

    const int qt = blockIdx.x, h = blockIdx.y, b = blockIdx.z;
    const int tid = threadIdx.x;
    const int w = tid >> 5, lane = tid & 31;
    const int g = lane >> 2, q4 = lane & 3;
    const int grp = lane >> 3, lr = lane & 7;
    const int q0 = qt * 128;
    const float scale = 0.10206207261596575f;

#pragma unroll
    for (int i = 0; i < 12; i++) {
        const int idx = i * 128 + tid;
        const int row = idx / 12, c = (idx % 12) * 8;
        *(uint4*)&Qs[row * 104 + c] =
            *(const uint4*)(qkv + (size_t)(b * TSEQ + q0 + row) * 2304 + h * 96 + c);
    }
    __syncthreads();

    uint32_t qa[2][6][4];
#pragma unroll
    for (int mi = 0; mi < 2; mi++)
#pragma unroll
        for (int k = 0; k < 6; k++) {
            const int row = w * 32 + mi * 16 + ((grp & 1) ? 8 : 0) + lr;
            const int col = k * 16 + ((grp & 2) ? 8 : 0);
            ldsm_x4(qa[mi][k][0], qa[mi][k][1], qa[mi][k][2], qa[mi][k][3],
                    smem_u32(&Qs[row * 104 + col]));
        }

    float oc[2][12][4];
#pragma unroll
    for (int mi = 0; mi < 2; mi++)
#pragma unroll
        for (int j = 0; j < 12; j++)
#pragma unroll
            for (int e = 0; e < 4; e++) oc[mi][j][e] = 0.f;
    float mst[4] = {-3e38f, -3e38f, -3e38f, -3e38f};
    float lst[4] = {0.f, 0.f, 0.f, 0.f};

    const int wrow_max = q0 + w * 32 + 31;
    const int nch = 2 * qt + 2;

    for (int jc = 0; jc < nch; ++jc) {
        const int kb = jc * 64;
        __syncthreads();

#pragma unroll
        for (int i = 0; i < 6; i++) {
            const int idx = i * 128 + tid;
            const int row = idx / 12, c = (idx % 12) * 8;
            const __half* base = qkv + (size_t)(b * TSEQ + kb + row) * 2304 + h * 96 + c;
            *(uint4*)&Ks[row * 104 + c] = *(const uint4*)(base + 768);
            *(uint4*)&Vs[row * 104 + c] = *(const uint4*)(base + 1536);
        }
        __syncthreads();

        if (kb > wrow_max) continue;

#pragma unroll
        for (int sub = 0; sub < 2; sub++) {
            const int ks0 = kb + sub * 32;
            if (ks0 > wrow_max) continue;

            float sc[2][4][4];
#pragma unroll
            for (int mi = 0; mi < 2; mi++)
#pragma unroll
                for (int j = 0; j < 4; j++)
#pragma unroll
                    for (int e = 0; e < 4; e++) sc[mi][j][e] = 0.f;
#pragma unroll
            for (int k = 0; k < 6; k++) {
#pragma unroll
                for (int jn = 0; jn < 2; jn++) {
                    const int key = sub * 32 + jn * 16 + lr + ((grp & 2) ? 8 : 0);
                    const int hd  = k * 16 + ((grp & 1) ? 8 : 0);
                    uint32_t b0, b1, b2, b3;
                    ldsm_x4(b0, b1, b2, b3, smem_u32(&Ks[key * 104 + hd]));
#pragma unroll
                    for (int mi = 0; mi < 2; mi++) {
                        mma16816(sc[mi][2 * jn],     qa[mi][k], b0, b1);
                        mma16816(sc[mi][2 * jn + 1], qa[mi][k], b2, b3);
                    }
                }
            }

            uint32_t pa[2][2][4];
            const bool diag = (ks0 + 31 > q0 + w * 32);
#pragma unroll
            for (int mi = 0; mi < 2; mi++) {
                const int rA = q0 + w * 32 + mi * 16 + g;
                const int rB = rA + 8;
                float mlocA = -3e38f, mlocB = -3e38f;
#pragma unroll
                for (int j = 0; j < 4; j++) {
                    const int c0 = ks0 + j * 8 + q4 * 2;
                    sc[mi][j][0] *= scale; sc[mi][j][1] *= scale;
                    sc[mi][j][2] *= scale; sc[mi][j][3] *= scale;
                    if (diag) {
                        if (c0     > rA) sc[mi][j][0] = -3e38f;
                        if (c0 + 1 > rA) sc[mi][j][1] = -3e38f;
                        if (c0     > rB) sc[mi][j][2] = -3e38f;
                        if (c0 + 1 > rB) sc[mi][j][3] = -3e38f;
                    }
                    mlocA = fmaxf(mlocA, fmaxf(sc[mi][j][0], sc[mi][j][1]));
                    mlocB = fmaxf(mlocB, fmaxf(sc[mi][j][2], sc[mi][j][3]));
                }
                mlocA = fmaxf(mlocA, __shfl_xor_sync(0xffffffffu, mlocA, 1));
                mlocA = fmaxf(mlocA, __shfl_xor_sync(0xffffffffu, mlocA, 2));
                mlocB = fmaxf(mlocB, __shfl_xor_sync(0xffffffffu, mlocB, 1));
                mlocB = fmaxf(mlocB, __shfl_xor_sync(0xffffffffu, mlocB, 2));
                const float mAn = fmaxf(mst[mi * 2],     mlocA);
                const float mBn = fmaxf(mst[mi * 2 + 1], mlocB);
                const float fA = __expf(mst[mi * 2]     - mAn);
                const float fB = __expf(mst[mi * 2 + 1] - mBn);
                mst[mi * 2] = mAn; mst[mi * 2 + 1] = mBn;

                float lsA = 0.f, lsB = 0.f;
#pragma unroll
                for (int k = 0; k < 2; k++) {
                    const float pA0 = __expf(sc[mi][2 * k][0] - mAn);
                    const float pA1 = __expf(sc[mi][2 * k][1] - mAn);
                    const float pB0 = __expf(sc[mi][2 * k][2] - mBn);
                    const float pB1 = __expf(sc[mi][2 * k][3] - mBn);
                    const float pA2 = __expf(sc[mi][2 * k + 1][0] - mAn);
                    const float pA3 = __expf(sc[mi][2 * k + 1][1] - mAn);
                    const float pB2 = __expf(sc[mi][2 * k + 1][2] - mBn);
                    const float pB3 = __expf(sc[mi][2 * k + 1][3] - mBn);
                    lsA += pA0 + pA1 + pA2 + pA3;
                    lsB += pB0 + pB1 + pB2 + pB3;
                    pa[mi][k][0] = packh2(pA0, pA1);
                    pa[mi][k][1] = packh2(pB0, pB1);
                    pa[mi][k][2] = packh2(pA2, pA3);
                    pa[mi][k][3] = packh2(pB2, pB3);
                }
                lsA += __shfl_xor_sync(0xffffffffu, lsA, 1);
                lsA += __shfl_xor_sync(0xffffffffu, lsA, 2);
                lsB += __shfl_xor_sync(0xffffffffu, lsB, 1);
                lsB += __shfl_xor_sync(0xffffffffu, lsB, 2);
                lst[mi * 2]     = lst[mi * 2]     * fA + lsA;
                lst[mi * 2 + 1] = lst[mi * 2 + 1] * fB + lsB;

#pragma unroll
                for (int j = 0; j < 12; j++) {
                    oc[mi][j][0] *= fA; oc[mi][j][1] *= fA;
                    oc[mi][j][2] *= fB; oc[mi][j][3] *= fB;
                }
            }

#pragma unroll
            for (int n = 0; n < 6; n++) {
#pragma unroll
                for (int k = 0; k < 2; k++) {
                    const int key = sub * 32 + k * 16 + lr + ((grp & 1) ? 8 : 0);
                    const int hd  = n * 16 + ((grp & 2) ? 8 : 0);
                    uint32_t b0, b1, b2, b3;
                    ldsm_x4_t(b0, b1, b2, b3, smem_u32(&Vs[key * 104 + hd]));
#pragma unroll
                    for (int mi = 0; mi < 2; mi++) {
                        mma16816(oc[mi][2 * n],     pa[mi][k], b0, b1);
                        mma16816(oc[mi][2 * n + 1], pa[mi][k], b2, b3);
                    }
                }
            }
        }
    }

#pragma unroll
    for (int mi = 0; mi < 2; mi++) {
        const int rA = q0 + w * 32 + mi * 16 + g;
        const int rB = rA + 8;
        const float invA = 1.0f / lst[mi * 2];
        const float invB = 1.0f / lst[mi * 2 + 1];
        __half* yA = y + (size_t)(b * TSEQ + rA) * 768 + h * 96;
        __half* yB = y + (size_t)(b * TSEQ + rB) * 768 + h * 96;
#pragma unroll
        for (int j = 0; j < 12; j++) {
            const int col = j * 8 + q4 * 2;
            *(uint32_t*)(yA + col) = packh2(oc[mi][j][0] * invA, oc[mi][j][1] * invA);
            *(uint32_t*)(yB + col) = packh2(oc[mi][j][2] * invB, oc[mi][j][3] * invB);
        }
    }
}

// ================= launch =================
extern "C" void kernel_launch(void* const* d_in, const int* in_sizes, int n_in,
                              void* d_out, int out_size)
{
    const float* x      = (const float*)d_in[0];
    const float* ln1_g  = (const float*)d_in[1];
    const float* ln1_b  = (const float*)d_in[2];
    const float* attn_w = (const float*)d_in[3];
    const float* attn_b = (const float*)d_in[4];
    const float* proj_w = (const float*)d_in[5];
    const float* proj_b = (const float*)d_in[6];
    const float* ln2_g  = (const float*)d_in[7];
    const float* ln2_b  = (const float*)d_in[8];
    const float* fc_w   = (const float*)d_in[9];
    const float* fc_b   = (const float*)d_in[10];
    const float* fc2_w  = (const float*)d_in[11];
    const float* fc2_b  = (const float*)d_in[12];
    float* out = (float*)d_out;

    __half *h, *qkv, *y, *h2, *wqkv, *wproj, *wfc, *wfc2;
    float *x1;
    cudaGetSymbolAddress((void**)&h,    g_h);
    cudaGetSymbolAddress((void**)&qkv,  g_qkv);
    cudaGetSymbolAddress((void**)&y,    g_y);
    cudaGetSymbolAddress((void**)&x1,   g_x1);
    cudaGetSymbolAddress((void**)&h2,   g_h2);
    cudaGetSymbolAddress((void**)&wqkv, g_wqkv);
    cudaGetSymbolAddress((void**)&wproj,g_wproj);
    cudaGetSymbolAddress((void**)&wfc,  g_wfc);
    cudaGetSymbolAddress((void**)&wfc2, g_wfc2);

    static bool attr_set = false;
    if (!attr_set) {
        cudaFuncSetAttribute(attn_kernel, cudaFuncAttributeMaxDynamicSharedMemorySize, ATTN_SMEM);
        cudaFuncSetAttribute(hgemm_kernel<0>, cudaFuncAttributeMaxDynamicSharedMemorySize, GEMM_SMEM);
        cudaFuncSetAttribute(hgemm_kernel<1>, cudaFuncAttributeMaxDynamicSharedMemorySize, GEMM_SMEM);
        cudaFuncSetAttribute(hgemm_kernel<2>, cudaFuncAttributeMaxDynamicSharedMemorySize, GEMM_SMEM);
        attr_set = true;
    }

    const int n0 = CDIM * 3 * CDIM / 4, n1 = CDIM * CDIM / 4;
    const int n2 = CDIM * 4 * CDIM / 4, n3 = 4 * CDIM * CDIM / 4;
    wconv4_kernel<<<(n0 + n1 + n2 + n3 + 255) / 256, 256>>>(
        attn_w, wqkv, n0, proj_w, wproj, n1, fc_w, wfc, n2, fc2_w, wfc2, n3);

    ln_kernel<<<MTOK, 256>>>(x, ln1_g, ln1_b, h);
    hgemm_kernel<0><<<dim3(2304 / 128, MTOK / 128), 128, GEMM_SMEM>>>(
        h, wqkv, attn_b, nullptr, nullptr, qkv, 2304, 768);
    attn_kernel<<<dim3(TSEQ / 128, NHEAD, BATCH), 128, ATTN_SMEM>>>(qkv, y);
    hgemm_kernel<1><<<dim3(768 / 128, MTOK / 128), 128, GEMM_SMEM>>>(
        y, wproj, proj_b, x, x1, nullptr, 768, 768);
    ln_kernel<<<MTOK, 256>>>(x1, ln2_g, ln2_b, h);
    hgemm_kernel<2><<<dim3(3072 / 128, MTOK / 128), 128, GEMM_SMEM>>>(
        h, wfc, fc_b, nullptr, nullptr, h2, 3072, 768);
    hgemm_kernel<1><<<dim3(768 / 128, MTOK / 128), 128, GEMM_SMEM>>>(
        h2, wfc2, fc2_b, x1, out, nullptr, 768, 3072);
}

// round 13
// speedup vs baseline: 1.0866x; 1.0866x over previous
#include <cuda_runtime.h>
#include <cuda_fp16.h>
#include <math.h>
#include <stdint.h>

#define MTOK  16384
#define CDIM  768
#define TSEQ  1024
#define BATCH 16
#define NHEAD 8
#define HDIM  96

// ================= scratch (no allocation allowed) =================
__device__ __half g_h  [(size_t)MTOK * CDIM];
__device__ __half g_qkv[(size_t)MTOK * 3 * CDIM];
__device__ __half g_y  [(size_t)MTOK * CDIM];
__device__ float  g_x1 [(size_t)MTOK * CDIM];
__device__ __half g_h2 [(size_t)MTOK * 4 * CDIM];
__device__ __half g_wqkv[(size_t)CDIM * 3 * CDIM];
__device__ __half g_wproj[(size_t)CDIM * CDIM];
__device__ __half g_wfc [(size_t)CDIM * 4 * CDIM];
__device__ __half g_wfc2[(size_t)4 * CDIM * CDIM];

__device__ __forceinline__ float gelu_f(float x) {
    const float x3 = x * x * x;
    return 0.5f * x * (1.0f + tanhf(0.7978845608028654f * (x + 0.044715f * x3)));
}
__device__ __forceinline__ uint32_t smem_u32(const void* p) {
    return (uint32_t)__cvta_generic_to_shared(p);
}
__device__ __forceinline__ void cp16(uint32_t dst, const void* src) {
    asm volatile("cp.async.cg.shared.global [%0], [%1], 16;\n" :: "r"(dst), "l"(src));
}
#define CP_COMMIT() asm volatile("cp.async.commit_group;\n" ::: "memory")
#define CP_WAIT0()  asm volatile("cp.async.wait_group 0;\n" ::: "memory")
#define CP_WAIT1()  asm volatile("cp.async.wait_group 1;\n" ::: "memory")

__device__ __forceinline__ void ldsm_x4(
    uint32_t& r0, uint32_t& r1, uint32_t& r2, uint32_t& r3, uint32_t addr)
{
    asm volatile("ldmatrix.sync.aligned.m8n8.x4.shared.b16 {%0,%1,%2,%3}, [%4];"
        : "=r"(r0), "=r"(r1), "=r"(r2), "=r"(r3) : "r"(addr));
}
__device__ __forceinline__ void ldsm_x4_t(
    uint32_t& r0, uint32_t& r1, uint32_t& r2, uint32_t& r3, uint32_t addr)
{
    asm volatile("ldmatrix.sync.aligned.m8n8.x4.trans.shared.b16 {%0,%1,%2,%3}, [%4];"
        : "=r"(r0), "=r"(r1), "=r"(r2), "=r"(r3) : "r"(addr));
}
__device__ __forceinline__ void mma16816(
    float* c, const uint32_t* a, uint32_t b0, uint32_t b1)
{
    asm volatile(
        "mma.sync.aligned.m16n8k16.row.col.f32.f16.f16.f32 "
        "{%0,%1,%2,%3},{%4,%5,%6,%7},{%8,%9},{%0,%1,%2,%3};"
        : "+f"(c[0]), "+f"(c[1]), "+f"(c[2]), "+f"(c[3])
        : "r"(a[0]), "r"(a[1]), "r"(a[2]), "r"(a[3]), "r"(b0), "r"(b1));
}
__device__ __forceinline__ uint32_t packh2(float a, float b) {
    __half2 h = __floats2half2_rn(a, b);
    return *(uint32_t*)&h;
}

// ================= fused weight f32 -> fp16 =================
__global__ __launch_bounds__(256) void wconv4_kernel(
    const float* __restrict__ s0, __half* __restrict__ d0, int n0,
    const float* __restrict__ s1, __half* __restrict__ d1, int n1,
    const float* __restrict__ s2, __half* __restrict__ d2, int n2,
    const float* __restrict__ s3, __half* __restrict__ d3, int n3)
{
    int i = blockIdx.x * 256 + threadIdx.x;
    const float* src; __half* dst;
    if (i < n0) { src = s0; dst = d0; }
    else if ((i -= n0) < n1) { src = s1; dst = d1; }
    else if ((i -= n1) < n2) { src = s2; dst = d2; }
    else if ((i -= n2) < n3) { src = s3; dst = d3; }
    else return;
    float4 v = ((const float4*)src)[i];
    __half2 a = __floats2half2_rn(v.x, v.y);
    __half2 b = __floats2half2_rn(v.z, v.w);
    *(uint2*)(dst + (size_t)i * 4) = make_uint2(*(uint32_t*)&a, *(uint32_t*)&b);
}

// ================= layernorm (f32 in -> fp16 out) =================
__global__ __launch_bounds__(256) void ln_kernel(
    const float* __restrict__ x, const float* __restrict__ g,
    const float* __restrict__ b, __half* __restrict__ out)
{
    const int row = blockIdx.x;
    const int tid = threadIdx.x;
    const float* xr = x + (size_t)row * CDIM;
    float vals[3];
    float s = 0.f, s2 = 0.f;
#pragma unroll
    for (int j = 0; j < 3; j++) {
        float t = xr[tid + 256 * j];
        vals[j] = t; s += t; s2 += t * t;
    }
#pragma unroll
    for (int o = 16; o > 0; o >>= 1) {
        s  += __shfl_xor_sync(0xffffffffu, s,  o);
        s2 += __shfl_xor_sync(0xffffffffu, s2, o);
    }
    __shared__ float rs[8], rs2[8];
    const int wid = tid >> 5, lane = tid & 31;
    if (lane == 0) { rs[wid] = s; rs2[wid] = s2; }
    __syncthreads();
    s = 0.f; s2 = 0.f;
#pragma unroll
    for (int w = 0; w < 8; w++) { s += rs[w]; s2 += rs2[w]; }
    const float mu  = s * (1.0f / CDIM);
    const float var = s2 * (1.0f / CDIM) - mu * mu;
    const float rstd = rsqrtf(var + 1e-5f);
#pragma unroll
    for (int j = 0; j < 3; j++) {
        const int c = tid + 256 * j;
        out[(size_t)row * CDIM + c] = __float2half_rn((vals[j] - mu) * rstd * g[c] + b[c]);
    }
}

// ===== raw-mma fp16 GEMM: BK=64, 2-stage, 3 CTAs/SM, staged epilogue =====
// block 128x128, 128 threads (4 warps 2x2), warp tile 64x64 = 4 m16 x 8 n8.
#define AS_OFF 0
#define BS_OFF (2 * 128 * 72 * 2)             // 36864
#define GEMM_SMEM (BS_OFF + 2 * 64 * 136 * 2) // 71680

// EPI: 0 = bias -> half ; 1 = bias+res(f32) -> f32 ; 2 = bias+gelu -> half
template <int EPI>
__global__ __launch_bounds__(128, 3) void hgemm_kernel(
    const __half* __restrict__ A, const __half* __restrict__ B,
    const float* __restrict__ bias, const float* __restrict__ res,
    float* __restrict__ Cf, __half* __restrict__ Ch, int N, int K)
{
    extern __shared__ char dsm[];
    __half* Asb = (__half*)(dsm + AS_OFF);    // [2][128][72]
    __half* Bsb = (__half*)(dsm + BS_OFF);    // [2][64][136]

    const int tid  = threadIdx.x;
    const int wid  = tid >> 5, lane = tid & 31;
    const int wm   = wid >> 1;
    const int wn   = wid & 1;
    const int g    = lane >> 2, q4 = lane & 3;
    const int grp  = lane >> 3, lr = lane & 7;
    const int bx   = blockIdx.x, by = blockIdx.y;

    float c[4][8][4];
#pragma unroll
    for (int mi = 0; mi < 4; mi++)
#pragma unroll
        for (int j = 0; j < 8; j++)
#pragma unroll
            for (int e = 0; e < 4; e++) c[mi][j][e] = 0.f;

    const __half* Agm = A + (size_t)(by * 128) * K;
    const __half* Bgm = B + bx * 128;
    const int nk = K >> 6;

    const int arb = tid >> 3, ak = (tid & 7) * 8;
    const int bkb = tid >> 4, bc = (tid & 15) * 8;

    auto copy_tile = [&](int s, int kt) {
        const __half* An = Agm + kt * 64;
        const __half* Bn = Bgm + (size_t)(kt * 64) * N;
#pragma unroll
        for (int it = 0; it < 8; it++) {
            const int ar = arb + it * 16;
            const int bk = bkb + it * 8;
            cp16(smem_u32(&Asb[((s * 128) + ar) * 72 + ak]), An + (size_t)ar * K + ak);
            cp16(smem_u32(&Bsb[((s * 64) + bk) * 136 + bc]), Bn + (size_t)bk * N + bc);
        }
    };

    copy_tile(0, 0); CP_COMMIT();

    const int a_row_off = wm * 64 + ((grp & 1) ? 8 : 0) + lr;  // + mi*16
    const int a_col_off = (grp & 2) ? 8 : 0;                   // + ks*16
    const int b_row_off = lr + ((grp & 1) ? 8 : 0);            // + ks*16
    const int b_col_off = wn * 64 + ((grp & 2) ? 8 : 0);       // + jn*16

    int buf = 0;
    for (int kt = 0; kt < nk; ++kt) {
        // issue next-tile copy into the buffer freed by iter kt-1's compute
        // (trailing barrier of prev iter guarantees no warp still reads it)
        if (kt + 1 < nk) { copy_tile(buf ^ 1, kt + 1); CP_COMMIT(); CP_WAIT1(); }
        else             { CP_WAIT0(); }
        __syncthreads();   // tile kt visible to all threads

#pragma unroll
        for (int ks = 0; ks < 4; ks++) {
            uint32_t a[4][4];
#pragma unroll
            for (int mi = 0; mi < 4; mi++)
                ldsm_x4(a[mi][0], a[mi][1], a[mi][2], a[mi][3],
                    smem_u32(&Asb[((buf * 128) + a_row_off + mi * 16) * 72
                                  + ks * 16 + a_col_off]));
#pragma unroll
            for (int jn = 0; jn < 4; jn++) {
                uint32_t b0, b1, b2, b3;
                ldsm_x4_t(b0, b1, b2, b3,
                    smem_u32(&Bsb[((buf * 64) + ks * 16 + b_row_off) * 136
                                  + jn * 16 + b_col_off]));
#pragma unroll
                for (int mi = 0; mi < 4; mi++) {
                    mma16816(c[mi][2 * jn],     a[mi], b0, b1);
                    mma16816(c[mi][2 * jn + 1], a[mi], b2, b3);
                }
            }
        }
        __syncthreads();   // compute done; next iter may overwrite buf
        buf ^= 1;
    }

    // ---- staged (coalesced) epilogue; staging overlaid on dead A smem ----
    float* mystg = (float*)dsm + wid * 256;   // 4KB total, inside Asb region
    const int r  = lane >> 1;
    const int cs = (lane & 1) * 8;
#pragma unroll
    for (int mi = 0; mi < 4; mi++) {
#pragma unroll
        for (int nj = 0; nj < 4; nj++) {
            // write the two n8 frags (j = 2nj, 2nj+1) into a 16x16 tile
#pragma unroll
            for (int half16 = 0; half16 < 2; half16++) {
                const float* cc = c[mi][2 * nj + half16];
                mystg[g * 16 + half16 * 8 + q4 * 2]           = cc[0];
                mystg[g * 16 + half16 * 8 + q4 * 2 + 1]       = cc[1];
                mystg[(g + 8) * 16 + half16 * 8 + q4 * 2]     = cc[2];
                mystg[(g + 8) * 16 + half16 * 8 + q4 * 2 + 1] = cc[3];
            }
            __syncwarp();
            const int row = by * 128 + wm * 64 + mi * 16 + r;
            const int col = bx * 128 + wn * 64 + nj * 16 + cs;
            const size_t base = (size_t)row * N + col;
            float4 b0 = *(const float4*)(bias + col);
            float4 b1 = *(const float4*)(bias + col + 4);
            float v[8];
#pragma unroll
            for (int u = 0; u < 8; u++) v[u] = mystg[r * 16 + cs + u];
            v[0] += b0.x; v[1] += b0.y; v[2] += b0.z; v[3] += b0.w;
            v[4] += b1.x; v[5] += b1.y; v[6] += b1.z; v[7] += b1.w;
            if (EPI == 1) {
                float4 r0 = *(const float4*)(res + base);
                float4 r1 = *(const float4*)(res + base + 4);
                v[0] += r0.x; v[1] += r0.y; v[2] += r0.z; v[3] += r0.w;
                v[4] += r1.x; v[5] += r1.y; v[6] += r1.z; v[7] += r1.w;
                *(float4*)(Cf + base)     = make_float4(v[0], v[1], v[2], v[3]);
                *(float4*)(Cf + base + 4) = make_float4(v[4], v[5], v[6], v[7]);
            } else {
                if (EPI == 2) {
#pragma unroll
                    for (int u = 0; u < 8; u++) v[u] = gelu_f(v[u]);
                }
                *(uint4*)(Ch + base) = make_uint4(
                    packh2(v[0], v[1]), packh2(v[2], v[3]),
                    packh2(v[4], v[5]), packh2(v[6], v[7]));
            }
            __syncwarp();
        }
    }
}

// ================= FA2 attention (unchanged from R11) =================
#define ATTN_SMEM ((128 + 64 + 64) * 104 * 2)

__global__ __launch_bounds__(128) void attn_kernel(
    const __half* __restrict__ qkv, __half* __restrict__ y)
{
    extern __shared__ __half asm_[];
    __half* Qs = asm_;
    __half* Ks = asm_ + 128 * 104;
    __half* Vs = asm_ + 192 * 104;

    const int qt = blockIdx.x, h = blockIdx.y, b = blockIdx.z;
    const int tid = threadIdx.x;
    const int w = tid >> 5, lane = tid & 31;
    const int g = lane >> 2, q4 = lane & 3;
    const int grp = lane >> 3, lr = lane & 7;
    const int q0 = qt * 128;
    const float scale = 0.10206207261596575f;

#pragma unroll
    for (int i = 0; i < 12; i++) {
        const int idx = i * 128 + tid;
        const int row = idx / 12, c = (idx % 12) * 8;
        *(uint4*)&Qs[row * 104 + c] =
            *(const uint4*)(qkv + (size_t)(b * TSEQ + q0 + row) * 2304 + h * 96 + c);
    }
    __syncthreads();

    uint32_t qa[2][6][4];
#pragma unroll
    for (int mi = 0; mi < 2; mi++)
#pragma unroll
        for (int k = 0; k < 6; k++) {
            const int row = w * 32 + mi * 16 + ((grp & 1) ? 8 : 0) + lr;
            const int col = k * 16 + ((grp & 2) ? 8 : 0);
            ldsm_x4(qa[mi][k][0], qa[mi][k][1], qa[mi][k][2], qa[mi][k][3],
                    smem_u32(&Qs[row * 104 + col]));
        }

    float oc[2][12][4];
#pragma unroll
    for (int mi = 0; mi < 2; mi++)
#pragma unroll
        for (int j = 0; j < 12; j++)
#pragma unroll
            for (int e = 0; e < 4; e++) oc[mi][j][e] = 0.f;
    float mst[4] = {-3e38f, -3e38f, -3e38f, -3e38f};
    float lst[4] = {0.f, 0.f, 0.f, 0.f};

    const int wrow_max = q0 + w * 32 + 31;
    const int nch = 2 * qt + 2;

    for (int jc = 0; jc < nch; ++jc) {
        const int kb = jc * 64;
        __syncthreads();

#pragma unroll
        for (int i = 0; i < 6; i++) {
            const int idx = i * 128 + tid;
            const int row = idx / 12, c = (idx % 12) * 8;
            const __half* base = qkv + (size_t)(b * TSEQ + kb + row) * 2304 + h * 96 + c;
            *(uint4*)&Ks[row * 104 + c] = *(const uint4*)(base + 768);
            *(uint4*)&Vs[row * 104 + c] = *(const uint4*)(base + 1536);
        }
        __syncthreads();

        if (kb > wrow_max) continue;

#pragma unroll
        for (int sub = 0; sub < 2; sub++) {
            const int ks0 = kb + sub * 32;
            if (ks0 > wrow_max) continue;

            float sc[2][4][4];
#pragma unroll
            for (int mi = 0; mi < 2; mi++)
#pragma unroll
                for (int j = 0; j < 4; j++)
#pragma unroll
                    for (int e = 0; e < 4; e++) sc[mi][j][e] = 0.f;
#pragma unroll
            for (int k = 0; k < 6; k++) {
#pragma unroll
                for (int jn = 0; jn < 2; jn++) {
                    const int key = sub * 32 + jn * 16 + lr + ((grp & 2) ? 8 : 0);
                    const int hd  = k * 16 + ((grp & 1) ? 8 : 0);
                    uint32_t b0, b1, b2, b3;
                    ldsm_x4(b0, b1, b2, b3, smem_u32(&Ks[key * 104 + hd]));
#pragma unroll
                    for (int mi = 0; mi < 2; mi++) {
                        mma16816(sc[mi][2 * jn],     qa[mi][k], b0, b1);
                        mma16816(sc[mi][2 * jn + 1], qa[mi][k], b2, b3);
                    }
                }
            }

            uint32_t pa[2][2][4];
            const bool diag = (ks0 + 31 > q0 + w * 32);
#pragma unroll
            for (int mi = 0; mi < 2; mi++) {
                const int rA = q0 + w * 32 + mi * 16 + g;
                const int rB = rA + 8;
                float mlocA = -3e38f, mlocB = -3e38f;
#pragma unroll
                for (int j = 0; j < 4; j++) {
                    const int c0 = ks0 + j * 8 + q4 * 2;
                    sc[mi][j][0] *= scale; sc[mi][j][1] *= scale;
                    sc[mi][j][2] *= scale; sc[mi][j][3] *= scale;
                    if (diag) {
                        if (c0     > rA) sc[mi][j][0] = -3e38f;
                        if (c0 + 1 > rA) sc[mi][j][1] = -3e38f;
                        if (c0     > rB) sc[mi][j][2] = -3e38f;
                        if (c0 + 1 > rB) sc[mi][j][3] = -3e38f;
                    }
                    mlocA = fmaxf(mlocA, fmaxf(sc[mi][j][0], sc[mi][j][1]));
                    mlocB = fmaxf(mlocB, fmaxf(sc[mi][j][2], sc[mi][j][3]));
                }
                mlocA = fmaxf(mlocA, __shfl_xor_sync(0xffffffffu, mlocA, 1));
                mlocA = fmaxf(mlocA, __shfl_xor_sync(0xffffffffu, mlocA, 2));
                mlocB = fmaxf(mlocB, __shfl_xor_sync(0xffffffffu, mlocB, 1));
                mlocB = fmaxf(mlocB, __shfl_xor_sync(0xffffffffu, mlocB, 2));
                const float mAn = fmaxf(mst[mi * 2],     mlocA);
                const float mBn = fmaxf(mst[mi * 2 + 1], mlocB);
                const float fA = __expf(mst[mi * 2]     - mAn);
                const float fB = __expf(mst[mi * 2 + 1] - mBn);
                mst[mi * 2] = mAn; mst[mi * 2 + 1] = mBn;

                float lsA = 0.f, lsB = 0.f;
#pragma unroll
                for (int k = 0; k < 2; k++) {
                    const float pA0 = __expf(sc[mi][2 * k][0] - mAn);
                    const float pA1 = __expf(sc[mi][2 * k][1] - mAn);
                    const float pB0 = __expf(sc[mi][2 * k][2] - mBn);
                    const float pB1 = __expf(sc[mi][2 * k][3] - mBn);
                    const float pA2 = __expf(sc[mi][2 * k + 1][0] - mAn);
                    const float pA3 = __expf(sc[mi][2 * k + 1][1] - mAn);
                    const float pB2 = __expf(sc[mi][2 * k + 1][2] - mBn);
                    const float pB3 = __expf(sc[mi][2 * k + 1][3] - mBn);
                    lsA += pA0 + pA1 + pA2 + pA3;
                    lsB += pB0 + pB1 + pB2 + pB3;
                    pa[mi][k][0] = packh2(pA0, pA1);
                    pa[mi][k][1] = packh2(pB0, pB1);
                    pa[mi][k][2] = packh2(pA2, pA3);
                    pa[mi][k][3] = packh2(pB2, pB3);
                }
                lsA += __shfl_xor_sync(0xffffffffu, lsA, 1);
                lsA += __shfl_xor_sync(0xffffffffu, lsA, 2);
                lsB += __shfl_xor_sync(0xffffffffu, lsB, 1);
                lsB += __shfl_xor_sync(0xffffffffu, lsB, 2);
                lst[mi * 2]     = lst[mi * 2]     * fA + lsA;
                lst[mi * 2 + 1] = lst[mi * 2 + 1] * fB + lsB;

#pragma unroll
                for (int j = 0; j < 12; j++) {
                    oc[mi][j][0] *= fA; oc[mi][j][1] *= fA;
                    oc[mi][j][2] *= fB; oc[mi][j][3] *= fB;
                }
            }

#pragma unroll
            for (int n = 0; n < 6; n++) {
#pragma unroll
                for (int k = 0; k < 2; k++) {
                    const int key = sub * 32 + k * 16 + lr + ((grp & 1) ? 8 : 0);
                    const int hd  = n * 16 + ((grp & 2) ? 8 : 0);
                    uint32_t b0, b1, b2, b3;
                    ldsm_x4_t(b0, b1, b2, b3, smem_u32(&Vs[key * 104 + hd]));
#pragma unroll
                    for (int mi = 0; mi < 2; mi++) {
                        mma16816(oc[mi][2 * n],     pa[mi][k], b0, b1);
                        mma16816(oc[mi][2 * n + 1], pa[mi][k], b2, b3);
                    }
                }
            }
        }
    }

#pragma unroll
    for (int mi = 0; mi < 2; mi++) {
        const int rA = q0 + w * 32 + mi * 16 + g;
        const int rB = rA + 8;
        const float invA = 1.0f / lst[mi * 2];
        const float invB = 1.0f / lst[mi * 2 + 1];
        __half* yA = y + (size_t)(b * TSEQ + rA) * 768 + h * 96;
        __half* yB = y + (size_t)(b * TSEQ + rB) * 768 + h * 96;
#pragma unroll
        for (int j = 0; j < 12; j++) {
            const int col = j * 8 + q4 * 2;
            *(uint32_t*)(yA + col) = packh2(oc[mi][j][0] * invA, oc[mi][j][1] * invA);
            *(uint32_t*)(yB + col) = packh2(oc[mi][j][2] * invB, oc[mi][j][3] * invB);
        }
    }
}

// ================= launch =================
extern "C" void kernel_launch(void* const* d_in, const int* in_sizes, int n_in,
                              void* d_out, int out_size)
{
    const float* x      = (const float*)d_in[0];
    const float* ln1_g  = (const float*)d_in[1];
    const float* ln1_b  = (const float*)d_in[2];
    const float* attn_w = (const float*)d_in[3];
    const float* attn_b = (const float*)d_in[4];
    const float* proj_w = (const float*)d_in[5];
    const float* proj_b = (const float*)d_in[6];
    const float* ln2_g  = (const float*)d_in[7];
    const float* ln2_b  = (const float*)d_in[8];
    const float* fc_w   = (const float*)d_in[9];
    const float* fc_b   = (const float*)d_in[10];
    const float* fc2_w  = (const float*)d_in[11];
    const float* fc2_b  = (const float*)d_in[12];
    float* out = (float*)d_out;

    __half *h, *qkv, *y, *h2, *wqkv, *wproj, *wfc, *wfc2;
    float *x1;
    cudaGetSymbolAddress((void**)&h,    g_h);
    cudaGetSymbolAddress((void**)&qkv,  g_qkv);
    cudaGetSymbolAddress((void**)&y,    g_y);
    cudaGetSymbolAddress((void**)&x1,   g_x1);
    cudaGetSymbolAddress((void**)&h2,   g_h2);
    cudaGetSymbolAddress((void**)&wqkv, g_wqkv);
    cudaGetSymbolAddress((void**)&wproj,g_wproj);
    cudaGetSymbolAddress((void**)&wfc,  g_wfc);
    cudaGetSymbolAddress((void**)&wfc2, g_wfc2);

    static bool attr_set = false;
    if (!attr_set) {
        cudaFuncSetAttribute(attn_kernel, cudaFuncAttributeMaxDynamicSharedMemorySize, ATTN_SMEM);
        cudaFuncSetAttribute(hgemm_kernel<0>, cudaFuncAttributeMaxDynamicSharedMemorySize, GEMM_SMEM);
        cudaFuncSetAttribute(hgemm_kernel<1>, cudaFuncAttributeMaxDynamicSharedMemorySize, GEMM_SMEM);
        cudaFuncSetAttribute(hgemm_kernel<2>, cudaFuncAttributeMaxDynamicSharedMemorySize, GEMM_SMEM);
        attr_set = true;
    }

    const int n0 = CDIM * 3 * CDIM / 4, n1 = CDIM * CDIM / 4;
    const int n2 = CDIM * 4 * CDIM / 4, n3 = 4 * CDIM * CDIM / 4;
    wconv4_kernel<<<(n0 + n1 + n2 + n3 + 255) / 256, 256>>>(
        attn_w, wqkv, n0, proj_w, wproj, n1, fc_w, wfc, n2, fc2_w, wfc2, n3);

    ln_kernel<<<MTOK, 256>>>(x, ln1_g, ln1_b, h);
    hgemm_kernel<0><<<dim3(2304 / 128, MTOK / 128), 128, GEMM_SMEM>>>(
        h, wqkv, attn_b, nullptr, nullptr, qkv, 2304, 768);
    attn_kernel<<<dim3(TSEQ / 128, NHEAD, BATCH), 128, ATTN_SMEM>>>(qkv, y);
    hgemm_kernel<1><<<dim3(768 / 128, MTOK / 128), 128, GEMM_SMEM>>>(
        y, wproj, proj_b, x, x1, nullptr, 768, 768);
    ln_kernel<<<MTOK, 256>>>(x1, ln2_g, ln2_b, h);
    hgemm_kernel<2><<<dim3(3072 / 128, MTOK / 128), 128, GEMM_SMEM>>>(
        h, wfc, fc_b, nullptr, nullptr, h2, 3072, 768);
    hgemm_kernel<1><<<dim3(768 / 128, MTOK / 128), 128, GEMM_SMEM>>>(
        h2, wfc2, fc2_b, x1, out, nullptr, 768, 3072);
}

// round 14
// speedup vs baseline: 1.1066x; 1.0184x over previous
#include <cuda_runtime.h>
#include <cuda_fp16.h>
#include <math.h>
#include <stdint.h>

#define MTOK  16384
#define CDIM  768
#define TSEQ  1024
#define BATCH 16
#define NHEAD 8
#define HDIM  96

// ================= scratch (no allocation allowed) =================
__device__ __half g_h  [(size_t)MTOK * CDIM];
__device__ __half g_qkv[(size_t)MTOK * 3 * CDIM];
__device__ __half g_y  [(size_t)MTOK * CDIM];
__device__ float  g_x1 [(size_t)MTOK * CDIM];
__device__ __half g_h2 [(size_t)MTOK * 4 * CDIM];
__device__ __half g_wqkv[(size_t)CDIM * 3 * CDIM];
__device__ __half g_wproj[(size_t)CDIM * CDIM];
__device__ __half g_wfc [(size_t)CDIM * 4 * CDIM];
__device__ __half g_wfc2[(size_t)4 * CDIM * CDIM];

__device__ __forceinline__ float gelu_f(float x) {
    const float x3 = x * x * x;
    return 0.5f * x * (1.0f + tanhf(0.7978845608028654f * (x + 0.044715f * x3)));
}
__device__ __forceinline__ uint32_t smem_u32(const void* p) {
    return (uint32_t)__cvta_generic_to_shared(p);
}
__device__ __forceinline__ void cp16(uint32_t dst, const void* src) {
    asm volatile("cp.async.cg.shared.global [%0], [%1], 16;\n" :: "r"(dst), "l"(src));
}
#define CP_COMMIT() asm volatile("cp.async.commit_group;\n" ::: "memory")
#define CP_WAIT0()  asm volatile("cp.async.wait_group 0;\n" ::: "memory")

__device__ __forceinline__ void ldsm_x4(
    uint32_t& r0, uint32_t& r1, uint32_t& r2, uint32_t& r3, uint32_t addr)
{
    asm volatile("ldmatrix.sync.aligned.m8n8.x4.shared.b16 {%0,%1,%2,%3}, [%4];"
        : "=r"(r0), "=r"(r1), "=r"(r2), "=r"(r3) : "r"(addr));
}
__device__ __forceinline__ void ldsm_x4_t(
    uint32_t& r0, uint32_t& r1, uint32_t& r2, uint32_t& r3, uint32_t addr)
{
    asm volatile("ldmatrix.sync.aligned.m8n8.x4.trans.shared.b16 {%0,%1,%2,%3}, [%4];"
        : "=r"(r0), "=r"(r1), "=r"(r2), "=r"(r3) : "r"(addr));
}
__device__ __forceinline__ void mma16816(
    float* c, const uint32_t* a, uint32_t b0, uint32_t b1)
{
    asm volatile(
        "mma.sync.aligned.m16n8k16.row.col.f32.f16.f16.f32 "
        "{%0,%1,%2,%3},{%4,%5,%6,%7},{%8,%9},{%0,%1,%2,%3};"
        : "+f"(c[0]), "+f"(c[1]), "+f"(c[2]), "+f"(c[3])
        : "r"(a[0]), "r"(a[1]), "r"(a[2]), "r"(a[3]), "r"(b0), "r"(b1));
}
__device__ __forceinline__ uint32_t packh2(float a, float b) {
    __half2 h = __floats2half2_rn(a, b);
    return *(uint32_t*)&h;
}

// ================= fused weight f32 -> fp16 =================
__global__ __launch_bounds__(256) void wconv4_kernel(
    const float* __restrict__ s0, __half* __restrict__ d0, int n0,
    const float* __restrict__ s1, __half* __restrict__ d1, int n1,
    const float* __restrict__ s2, __half* __restrict__ d2, int n2,
    const float* __restrict__ s3, __half* __restrict__ d3, int n3)
{
    int i = blockIdx.x * 256 + threadIdx.x;
    const float* src; __half* dst;
    if (i < n0) { src = s0; dst = d0; }
    else if ((i -= n0) < n1) { src = s1; dst = d1; }
    else if ((i -= n1) < n2) { src = s2; dst = d2; }
    else if ((i -= n2) < n3) { src = s3; dst = d3; }
    else return;
    float4 v = ((const float4*)src)[i];
    __half2 a = __floats2half2_rn(v.x, v.y);
    __half2 b = __floats2half2_rn(v.z, v.w);
    *(uint2*)(dst + (size_t)i * 4) = make_uint2(*(uint32_t*)&a, *(uint32_t*)&b);
}

// ================= layernorm (f32 in -> fp16 out) =================
__global__ __launch_bounds__(256) void ln_kernel(
    const float* __restrict__ x, const float* __restrict__ g,
    const float* __restrict__ b, __half* __restrict__ out)
{
    const int row = blockIdx.x;
    const int tid = threadIdx.x;
    const float* xr = x + (size_t)row * CDIM;
    float vals[3];
    float s = 0.f, s2 = 0.f;
#pragma unroll
    for (int j = 0; j < 3; j++) {
        float t = xr[tid + 256 * j];
        vals[j] = t; s += t; s2 += t * t;
    }
#pragma unroll
    for (int o = 16; o > 0; o >>= 1) {
        s  += __shfl_xor_sync(0xffffffffu, s,  o);
        s2 += __shfl_xor_sync(0xffffffffu, s2, o);
    }
    __shared__ float rs[8], rs2[8];
    const int wid = tid >> 5, lane = tid & 31;
    if (lane == 0) { rs[wid] = s; rs2[wid] = s2; }
    __syncthreads();
    s = 0.f; s2 = 0.f;
#pragma unroll
    for (int w = 0; w < 8; w++) { s += rs[w]; s2 += rs2[w]; }
    const float mu  = s * (1.0f / CDIM);
    const float var = s2 * (1.0f / CDIM) - mu * mu;
    const float rstd = rsqrtf(var + 1e-5f);
#pragma unroll
    for (int j = 0; j < 3; j++) {
        const int c = tid + 256 * j;
        out[(size_t)row * CDIM + c] = __float2half_rn((vals[j] - mu) * rstd * g[c] + b[c]);
    }
}

// ===== raw-mma fp16 GEMM: BK=64, 2-stage, 3 CTAs/SM, 1 barrier/iter =====
// block 128x128, 128 threads (4 warps 2x2), warp tile 64x64 = 4 m16 x 8 n8.
#define AS_OFF 0
#define BS_OFF (2 * 128 * 72 * 2)             // 36864
#define GEMM_SMEM (BS_OFF + 2 * 64 * 136 * 2) // 71680

// EPI: 0 = bias -> half ; 1 = bias+res(f32) -> f32 ; 2 = bias+gelu -> half
template <int EPI>
__global__ __launch_bounds__(128, 3) void hgemm_kernel(
    const __half* __restrict__ A, const __half* __restrict__ B,
    const float* __restrict__ bias, const float* __restrict__ res,
    float* __restrict__ Cf, __half* __restrict__ Ch, int N, int K)
{
    extern __shared__ char dsm[];
    __half* Asb = (__half*)(dsm + AS_OFF);    // [2][128][72]
    __half* Bsb = (__half*)(dsm + BS_OFF);    // [2][64][136]

    const int tid  = threadIdx.x;
    const int wid  = tid >> 5, lane = tid & 31;
    const int wm   = wid >> 1;
    const int wn   = wid & 1;
    const int g    = lane >> 2, q4 = lane & 3;
    const int grp  = lane >> 3, lr = lane & 7;
    const int bx   = blockIdx.x, by = blockIdx.y;

    float c[4][8][4];
#pragma unroll
    for (int mi = 0; mi < 4; mi++)
#pragma unroll
        for (int j = 0; j < 8; j++)
#pragma unroll
            for (int e = 0; e < 4; e++) c[mi][j][e] = 0.f;

    const __half* Agm = A + (size_t)(by * 128) * K;
    const __half* Bgm = B + bx * 128;
    const int nk = K >> 6;

    const int arb = tid >> 3, ak = (tid & 7) * 8;
    const int bkb = tid >> 4, bc = (tid & 15) * 8;

    auto copy_tile = [&](int s, int kt) {
        const __half* An = Agm + kt * 64;
        const __half* Bn = Bgm + (size_t)(kt * 64) * N;
#pragma unroll
        for (int it = 0; it < 8; it++) {
            const int ar = arb + it * 16;
            const int bk = bkb + it * 8;
            cp16(smem_u32(&Asb[((s * 128) + ar) * 72 + ak]), An + (size_t)ar * K + ak);
            cp16(smem_u32(&Bsb[((s * 64) + bk) * 136 + bc]), Bn + (size_t)bk * N + bc);
        }
    };

    // prologue: tile 0 ready before loop
    copy_tile(0, 0); CP_COMMIT(); CP_WAIT0();
    __syncthreads();

    const int a_row_off = wm * 64 + ((grp & 1) ? 8 : 0) + lr;  // + mi*16
    const int a_col_off = (grp & 2) ? 8 : 0;                   // + ks*16
    const int b_row_off = lr + ((grp & 1) ? 8 : 0);            // + ks*16
    const int b_col_off = wn * 64 + ((grp & 2) ? 8 : 0);       // + jn*16

    int buf = 0;
    for (int kt = 0; kt < nk; ++kt) {
        // overlap next-tile copy under this tile's compute.
        // buf^1 is free: last read at iter kt-1, covered by trailing barrier.
        if (kt + 1 < nk) { copy_tile(buf ^ 1, kt + 1); CP_COMMIT(); }

#pragma unroll
        for (int ks = 0; ks < 4; ks++) {
            uint32_t a[4][4];
#pragma unroll
            for (int mi = 0; mi < 4; mi++)
                ldsm_x4(a[mi][0], a[mi][1], a[mi][2], a[mi][3],
                    smem_u32(&Asb[((buf * 128) + a_row_off + mi * 16) * 72
                                  + ks * 16 + a_col_off]));
#pragma unroll
            for (int jn = 0; jn < 4; jn++) {
                uint32_t b0, b1, b2, b3;
                ldsm_x4_t(b0, b1, b2, b3,
                    smem_u32(&Bsb[((buf * 64) + ks * 16 + b_row_off) * 136
                                  + jn * 16 + b_col_off]));
#pragma unroll
                for (int mi = 0; mi < 4; mi++) {
                    mma16816(c[mi][2 * jn],     a[mi], b0, b1);
                    mma16816(c[mi][2 * jn + 1], a[mi], b2, b3);
                }
            }
        }

        CP_WAIT0();        // next tile landed (overlapped with the MMAs above)
        __syncthreads();   // all warps done reading buf + see tile kt+1
        buf ^= 1;
    }

    // ---- staged (coalesced) epilogue; staging overlaid on dead A smem ----
    float* mystg = (float*)dsm + wid * 256;   // 4KB total, inside Asb region
    const int r  = lane >> 1;
    const int cs = (lane & 1) * 8;
#pragma unroll
    for (int mi = 0; mi < 4; mi++) {
#pragma unroll
        for (int nj = 0; nj < 4; nj++) {
#pragma unroll
            for (int half16 = 0; half16 < 2; half16++) {
                const float* cc = c[mi][2 * nj + half16];
                mystg[g * 16 + half16 * 8 + q4 * 2]           = cc[0];
                mystg[g * 16 + half16 * 8 + q4 * 2 + 1]       = cc[1];
                mystg[(g + 8) * 16 + half16 * 8 + q4 * 2]     = cc[2];
                mystg[(g + 8) * 16 + half16 * 8 + q4 * 2 + 1] = cc[3];
            }
            __syncwarp();
            const int row = by * 128 + wm * 64 + mi * 16 + r;
            const int col = bx * 128 + wn * 64 + nj * 16 + cs;
            const size_t base = (size_t)row * N + col;
            float4 b0 = *(const float4*)(bias + col);
            float4 b1 = *(const float4*)(bias + col + 4);
            float v[8];
#pragma unroll
            for (int u = 0; u < 8; u++) v[u] = mystg[r * 16 + cs + u];
            v[0] += b0.x; v[1] += b0.y; v[2] += b0.z; v[3] += b0.w;
            v[4] += b1.x; v[5] += b1.y; v[6] += b1.z; v[7] += b1.w;
            if (EPI == 1) {
                float4 r0 = *(const float4*)(res + base);
                float4 r1 = *(const float4*)(res + base + 4);
                v[0] += r0.x; v[1] += r0.y; v[2] += r0.z; v[3] += r0.w;
                v[4] += r1.x; v[5] += r1.y; v[6] += r1.z; v[7] += r1.w;
                *(float4*)(Cf + base)     = make_float4(v[0], v[1], v[2], v[3]);
                *(float4*)(Cf + base + 4) = make_float4(v[4], v[5], v[6], v[7]);
            } else {
                if (EPI == 2) {
#pragma unroll
                    for (int u = 0; u < 8; u++) v[u] = gelu_f(v[u]);
                }
                *(uint4*)(Ch + base) = make_uint4(
                    packh2(v[0], v[1]), packh2(v[2], v[3]),
                    packh2(v[4], v[5]), packh2(v[6], v[7]));
            }
            __syncwarp();
        }
    }
}

// ================= FA2 attention (unchanged from R11/R13) =================
#define ATTN_SMEM ((128 + 64 + 64) * 104 * 2)

__global__ __launch_bounds__(128) void attn_kernel(
    const __half* __restrict__ qkv, __half* __restrict__ y)
{
    extern __shared__ __half asm_[];
    __half* Qs = asm_;
    __half* Ks = asm_ + 128 * 104;
    __half* Vs = asm_ + 192 * 104;

    const int qt = blockIdx.x, h = blockIdx.y, b = blockIdx.z;
    const int tid = threadIdx.x;
    const int w = tid >> 5, lane = tid & 31;
    const int g = lane >> 2, q4 = lane & 3;
    const int grp = lane >> 3, lr = lane & 7;
    const int q0 = qt * 128;
    const float scale = 0.10206207261596575f;

#pragma unroll
    for (int i = 0; i < 12; i++) {
        const int idx = i * 128 + tid;
        const int row = idx / 12, c = (idx % 12) * 8;
        *(uint4*)&Qs[row * 104 + c] =
            *(const uint4*)(qkv + (size_t)(b * TSEQ + q0 + row) * 2304 + h * 96 + c);
    }
    __syncthreads();

    uint32_t qa[2][6][4];
#pragma unroll
    for (int mi = 0; mi < 2; mi++)
#pragma unroll
        for (int k = 0; k < 6; k++) {
            const int row = w * 32 + mi * 16 + ((grp & 1) ? 8 : 0) + lr;
            const int col = k * 16 + ((grp & 2) ? 8 : 0);
            ldsm_x4(qa[mi][k][0], qa[mi][k][1], qa[mi][k][2], qa[mi][k][3],
                    smem_u32(&Qs[row * 104 + col]));
        }

    float oc[2][12][4];
#pragma unroll
    for (int mi = 0; mi < 2; mi++)
#pragma unroll
        for (int j = 0; j < 12; j++)
#pragma unroll
            for (int e = 0; e < 4; e++) oc[mi][j][e] = 0.f;
    float mst[4] = {-3e38f, -3e38f, -3e38f, -3e38f};
    float lst[4] = {0.f, 0.f, 0.f, 0.f};

    const int wrow_max = q0 + w * 32 + 31;
    const int nch = 2 * qt + 2;

    for (int jc = 0; jc < nch; ++jc) {
        const int kb = jc * 64;
        __syncthreads();

#pragma unroll
        for (int i = 0; i < 6; i++) {
            const int idx = i * 128 + tid;
            const int row = idx / 12, c = (idx % 12) * 8;
            const __half* base = qkv + (size_t)(b * TSEQ + kb + row) * 2304 + h * 96 + c;
            *(uint4*)&Ks[row * 104 + c] = *(const uint4*)(base + 768);
            *(uint4*)&Vs[row * 104 + c] = *(const uint4*)(base + 1536);
        }
        __syncthreads();

        if (kb > wrow_max) continue;

#pragma unroll
        for (int sub = 0; sub < 2; sub++) {
            const int ks0 = kb + sub * 32;
            if (ks0 > wrow_max) continue;

            float sc[2][4][4];
#pragma unroll
            for (int mi = 0; mi < 2; mi++)
#pragma unroll
                for (int j = 0; j < 4; j++)
#pragma unroll
                    for (int e = 0; e < 4; e++) sc[mi][j][e] = 0.f;
#pragma unroll
            for (int k = 0; k < 6; k++) {
#pragma unroll
                for (int jn = 0; jn < 2; jn++) {
                    const int key = sub * 32 + jn * 16 + lr + ((grp & 2) ? 8 : 0);
                    const int hd  = k * 16 + ((grp & 1) ? 8 : 0);
                    uint32_t b0, b1, b2, b3;
                    ldsm_x4(b0, b1, b2, b3, smem_u32(&Ks[key * 104 + hd]));
#pragma unroll
                    for (int mi = 0; mi < 2; mi++) {
                        mma16816(sc[mi][2 * jn],     qa[mi][k], b0, b1);
                        mma16816(sc[mi][2 * jn + 1], qa[mi][k], b2, b3);
                    }
                }
            }

            uint32_t pa[2][2][4];
            const bool diag = (ks0 + 31 > q0 + w * 32);
#pragma unroll
            for (int mi = 0; mi < 2; mi++) {
                const int rA = q0 + w * 32 + mi * 16 + g;
                const int rB = rA + 8;
                float mlocA = -3e38f, mlocB = -3e38f;
#pragma unroll
                for (int j = 0; j < 4; j++) {
                    const int c0 = ks0 + j * 8 + q4 * 2;
                    sc[mi][j][0] *= scale; sc[mi][j][1] *= scale;
                    sc[mi][j][2] *= scale; sc[mi][j][3] *= scale;
                    if (diag) {
                        if (c0     > rA) sc[mi][j][0] = -3e38f;
                        if (c0 + 1 > rA) sc[mi][j][1] = -3e38f;
                        if (c0     > rB) sc[mi][j][2] = -3e38f;
                        if (c0 + 1 > rB) sc[mi][j][3] = -3e38f;
                    }
                    mlocA = fmaxf(mlocA, fmaxf(sc[mi][j][0], sc[mi][j][1]));
                    mlocB = fmaxf(mlocB, fmaxf(sc[mi][j][2], sc[mi][j][3]));
                }
                mlocA = fmaxf(mlocA, __shfl_xor_sync(0xffffffffu, mlocA, 1));
                mlocA = fmaxf(mlocA, __shfl_xor_sync(0xffffffffu, mlocA, 2));
                mlocB = fmaxf(mlocB, __shfl_xor_sync(0xffffffffu, mlocB, 1));
                mlocB = fmaxf(mlocB, __shfl_xor_sync(0xffffffffu, mlocB, 2));
                const float mAn = fmaxf(mst[mi * 2],     mlocA);
                const float mBn = fmaxf(mst[mi * 2 + 1], mlocB);
                const float fA = __expf(mst[mi * 2]     - mAn);
                const float fB = __expf(mst[mi * 2 + 1] - mBn);
                mst[mi * 2] = mAn; mst[mi * 2 + 1] = mBn;

                float lsA = 0.f, lsB = 0.f;
#pragma unroll
                for (int k = 0; k < 2; k++) {
                    const float pA0 = __expf(sc[mi][2 * k][0] - mAn);
                    const float pA1 = __expf(sc[mi][2 * k][1] - mAn);
                    const float pB0 = __expf(sc[mi][2 * k][2] - mBn);
                    const float pB1 = __expf(sc[mi][2 * k][3] - mBn);
                    const float pA2 = __expf(sc[mi][2 * k + 1][0] - mAn);
                    const float pA3 = __expf(sc[mi][2 * k + 1][1] - mAn);
                    const float pB2 = __expf(sc[mi][2 * k + 1][2] - mBn);
                    const float pB3 = __expf(sc[mi][2 * k + 1][3] - mBn);
                    lsA += pA0 + pA1 + pA2 + pA3;
                    lsB += pB0 + pB1 + pB2 + pB3;
                    pa[mi][k][0] = packh2(pA0, pA1);
                    pa[mi][k][1] = packh2(pB0, pB1);
                    pa[mi][k][2] = packh2(pA2, pA3);
                    pa[mi][k][3] = packh2(pB2, pB3);
                }
                lsA += __shfl_xor_sync(0xffffffffu, lsA, 1);
                lsA += __shfl_xor_sync(0xffffffffu, lsA, 2);
                lsB += __shfl_xor_sync(0xffffffffu, lsB, 1);
                lsB += __shfl_xor_sync(0xffffffffu, lsB, 2);
                lst[mi * 2]     = lst[mi * 2]     * fA + lsA;
                lst[mi * 2 + 1] = lst[mi * 2 + 1] * fB + lsB;

#pragma unroll
                for (int j = 0; j < 12; j++) {
                    oc[mi][j][0] *= fA; oc[mi][j][1] *= fA;
                    oc[mi][j][2] *= fB; oc[mi][j][3] *= fB;
                }
            }

#pragma unroll
            for (int n = 0; n < 6; n++) {
#pragma unroll
                for (int k = 0; k < 2; k++) {
                    const int key = sub * 32 + k * 16 + lr + ((grp & 1) ? 8 : 0);
                    const int hd  = n * 16 + ((grp & 2) ? 8 : 0);
                    uint32_t b0, b1, b2, b3;
                    ldsm_x4_t(b0, b1, b2, b3, smem_u32(&Vs[key * 104 + hd]));
#pragma unroll
                    for (int mi = 0; mi < 2; mi++) {
                        mma16816(oc[mi][2 * n],     pa[mi][k], b0, b1);
                        mma16816(oc[mi][2 * n + 1], pa[mi][k], b2, b3);
                    }
                }
            }
        }
    }

#pragma unroll
    for (int mi = 0; mi < 2; mi++) {
        const int rA = q0 + w * 32 + mi * 16 + g;
        const int rB = rA + 8;
        const float invA = 1.0f / lst[mi * 2];
        const float invB = 1.0f / lst[mi * 2 + 1];
        __half* yA = y + (size_t)(b * TSEQ + rA) * 768 + h * 96;
        __half* yB = y + (size_t)(b * TSEQ + rB) * 768 + h * 96;
#pragma unroll
        for (int j = 0; j < 12; j++) {
            const int col = j * 8 + q4 * 2;
            *(uint32_t*)(yA + col) = packh2(oc[mi][j][0] * invA, oc[mi][j][1] * invA);
            *(uint32_t*)(yB + col) = packh2(oc[mi][j][2] * invB, oc[mi][j][3] * invB);
        }
    }
}

// ================= launch =================
extern "C" void kernel_launch(void* const* d_in, const int* in_sizes, int n_in,
                              void* d_out, int out_size)
{
    const float* x      = (const float*)d_in[0];
    const float* ln1_g  = (const float*)d_in[1];
    const float* ln1_b  = (const float*)d_in[2];
    const float* attn_w = (const float*)d_in[3];
    const float* attn_b = (const float*)d_in[4];
    const float* proj_w = (const float*)d_in[5];
    const float* proj_b = (const float*)d_in[6];
    const float* ln2_g  = (const float*)d_in[7];
    const float* ln2_b  = (const float*)d_in[8];
    const float* fc_w   = (const float*)d_in[9];
    const float* fc_b   = (const float*)d_in[10];
    const float* fc2_w  = (const float*)d_in[11];
    const float* fc2_b  = (const float*)d_in[12];
    float* out = (float*)d_out;

    __half *h, *qkv, *y, *h2, *wqkv, *wproj, *wfc, *wfc2;
    float *x1;
    cudaGetSymbolAddress((void**)&h,    g_h);
    cudaGetSymbolAddress((void**)&qkv,  g_qkv);
    cudaGetSymbolAddress((void**)&y,    g_y);
    cudaGetSymbolAddress((void**)&x1,   g_x1);
    cudaGetSymbolAddress((void**)&h2,   g_h2);
    cudaGetSymbolAddress((void**)&wqkv, g_wqkv);
    cudaGetSymbolAddress((void**)&wproj,g_wproj);
    cudaGetSymbolAddress((void**)&wfc,  g_wfc);
    cudaGetSymbolAddress((void**)&wfc2, g_wfc2);

    static bool attr_set = false;
    if (!attr_set) {
        cudaFuncSetAttribute(attn_kernel, cudaFuncAttributeMaxDynamicSharedMemorySize, ATTN_SMEM);
        cudaFuncSetAttribute(hgemm_kernel<0>, cudaFuncAttributeMaxDynamicSharedMemorySize, GEMM_SMEM);
        cudaFuncSetAttribute(hgemm_kernel<1>, cudaFuncAttributeMaxDynamicSharedMemorySize, GEMM_SMEM);
        cudaFuncSetAttribute(hgemm_kernel<2>, cudaFuncAttributeMaxDynamicSharedMemorySize, GEMM_SMEM);
        attr_set = true;
    }

    const int n0 = CDIM * 3 * CDIM / 4, n1 = CDIM * CDIM / 4;
    const int n2 = CDIM * 4 * CDIM / 4, n3 = 4 * CDIM * CDIM / 4;
    wconv4_kernel<<<(n0 + n1 + n2 + n3 + 255) / 256, 256>>>(
        attn_w, wqkv, n0, proj_w, wproj, n1, fc_w, wfc, n2, fc2_w, wfc2, n3);

    ln_kernel<<<MTOK, 256>>>(x, ln1_g, ln1_b, h);
    hgemm_kernel<0><<<dim3(2304 / 128, MTOK / 128), 128, GEMM_SMEM>>>(
        h, wqkv, attn_b, nullptr, nullptr, qkv, 2304, 768);
    attn_kernel<<<dim3(TSEQ / 128, NHEAD, BATCH), 128, ATTN_SMEM>>>(qkv, y);
    hgemm_kernel<1><<<dim3(768 / 128, MTOK / 128), 128, GEMM_SMEM>>>(
        y, wproj, proj_b, x, x1, nullptr, 768, 768);
    ln_kernel<<<MTOK, 256>>>(x1, ln2_g, ln2_b, h);
    hgemm_kernel<2><<<dim3(3072 / 128, MTOK / 128), 128, GEMM_SMEM>>>(
        h, wfc, fc_b, nullptr, nullptr, h2, 3072, 768);
    hgemm_kernel<1><<<dim3(768 / 128, MTOK / 128), 128, GEMM_SMEM>>>(
        h2, wfc2, fc2_b, x1, out, nullptr, 768, 3072);
}